// round 17
// baseline (speedup 1.0000x reference)
#include <cuda_runtime.h>
#include <cuda_bf16.h>
#include <cstdint>

// Algebraic collapse (alpha=1): exp(lse) = sum_r exp(ln(x_r+1)+k_r+5) = sum_r (x_r+1)e^{k_r+5}
// -> out[m,co] = sum_r A[m,r]*W''[r,co] + C[co],  W'' = e^{k+5}-dw,
//    C = sum_r e^{k_r+5} - dx*sum_r k_r + bias.
// R17: M-tile = 56 px = exactly 2 image rows (grid 14x8, no batch crossing).
// Warps 0-7: coalesced unique-x tile load -> smem -> A build (kills the 3.8x
// redundant scattered LDG of R16). Warps 8-15: weight exp -> sB, concurrent.
// A rows 56..63 zero-padded for the 64-row HMMA tile.

__device__ __forceinline__ uint32_t smem_u32(const void* p) {
    uint32_t a;
    asm("{ .reg .u64 t; cvta.to.shared.u64 t, %1; cvt.u32.u64 %0, t; }" : "=r"(a) : "l"(p));
    return a;
}
__device__ __forceinline__ void ldmx4(uint32_t* r, uint32_t addr) {
    asm volatile("ldmatrix.sync.aligned.m8n8.x4.shared.b16 {%0,%1,%2,%3}, [%4];"
                 : "=r"(r[0]), "=r"(r[1]), "=r"(r[2]), "=r"(r[3]) : "r"(addr));
}
__device__ __forceinline__ void mma16816(float* d, const uint32_t* a,
                                         uint32_t b0, uint32_t b1) {
    asm volatile(
        "mma.sync.aligned.m16n8k16.row.col.f32.bf16.bf16.f32 "
        "{%0,%1,%2,%3}, {%4,%5,%6,%7}, {%8,%9}, {%0,%1,%2,%3};"
        : "+f"(d[0]), "+f"(d[1]), "+f"(d[2]), "+f"(d[3])
        : "r"(a[0]), "r"(a[1]), "r"(a[2]), "r"(a[3]), "r"(b0), "r"(b1));
}
__device__ __forceinline__ uint32_t pack_bf16x2(float a, float b) {
    __nv_bfloat162 t = __floats2bfloat162_rn(a, b);
    return *reinterpret_cast<uint32_t*>(&t);
}

constexpr int STRB  = 592;                 // 37*16B A/B rows: conflict-free ldmatrix
constexpr int OFF_X = 0;                   // sXt fp32 [32cin][4rows][33cols] = 16896
constexpr int OFF_A = 16896;               // 64*592 = 37888 ; sD aliases this later
constexpr int OFF_B = 54784;               // 64*592 = 37888
constexpr int OFF_C = 92672;               // 64 floats
constexpr int OFF_R = 92928;               // reduce scratch 2*4*64 floats = 2048
constexpr int SMEMB = 94976;
constexpr int CNT   = 512;                 // 16 warps

__global__ void __launch_bounds__(CNT) fused_conv_kernel(
    const float* __restrict__ x, const float* __restrict__ k,
    const float* __restrict__ bias,
    const float* __restrict__ dxp, const float* __restrict__ dwp,
    float* __restrict__ out)
{
    extern __shared__ __align__(16) char sm[];
    const uint32_t smb = smem_u32(sm);
    const int tid  = threadIdx.x;
    const int wid  = tid >> 5;
    const int lane = tid & 31;
    const int ti   = blockIdx.x;             // 0..13: image-row pair
    const int b    = blockIdx.y;             // 0..7
    const int h0   = ti * 2;                 // first output row of tile

    if (tid < 256) {
        // ============ warps 0-7: x tile load + A build ============
        float* sXt = reinterpret_cast<float*>(sm + OFF_X);
        const float* xb = x + (size_t)b * 32 * 784;
        // coalesced unique-x load: rows h0-1..h0+2, cols -1..28 (cc-1), stride-33
        #pragma unroll
        for (int i = 0; i < 17; i++) {
            int idx = tid + 256 * i;
            if (idx < 4224) {
                int cin = idx / 132;
                int rem = idx - cin * 132;
                int rr  = rem / 33;
                int cc  = rem - rr * 33;
                int gr  = h0 - 1 + rr;
                float v = 0.f;
                if (cc >= 1 && cc <= 28 && (unsigned)gr < 28u)
                    v = xb[cin * 784 + gr * 28 + cc - 1];
                sXt[idx] = v;
            }
        }
        asm volatile("bar.sync 1, 256;" ::: "memory");   // warps 0-7 only

        // A build: thread -> pixel j = tid>>2, chunks c36 = lane4*9 + q
        {
            const int j     = tid >> 2;      // 0..63
            const int lane4 = tid & 3;
            char* dA = sm + OFF_A + j * STRB;
            if (j < 56) {
                const int hadd = (j >= 28) ? 1 : 0;
                const int w    = j - 28 * hadd;
                #pragma unroll
                for (int q = 0; q < 9; q++) {
                    int c36 = lane4 * 9 + q;
                    int seg = c36 >> 2, c8 = c36 & 3;
                    int kh = seg / 3, kw = seg - kh * 3;
                    const float* p = sXt + c8 * 1056 + (hadd + kh) * 33 + (w + kw);
                    uint4 v;
                    v.x = pack_bf16x2(p[0],   p[132]);
                    v.y = pack_bf16x2(p[264], p[396]);
                    v.z = pack_bf16x2(p[528], p[660]);
                    v.w = pack_bf16x2(p[792], p[924]);
                    *reinterpret_cast<uint4*>(dA + c36 * 16) = v;
                }
            } else {                          // zero-pad rows 56..63
                uint4 z = make_uint4(0, 0, 0, 0);
                #pragma unroll
                for (int q = 0; q < 9; q++)
                    *reinterpret_cast<uint4*>(dA + (lane4 * 9 + q) * 16) = z;
            }
        }
    } else {
        // ============ warps 8-15: weight transform -> sB, concurrent ============
        const int tid2 = tid & 255;
        const int co   = tid2 & 63;
        const int g    = tid2 >> 6;           // 0..3
        const float dw = dwp[0];
        __nv_bfloat16* sBrow = reinterpret_cast<__nv_bfloat16*>(sm + OFF_B + co * STRB);
        float pse = 0.f, psk = 0.f;
        #pragma unroll 8
        for (int j = 0; j < 72; j++) {
            int r = g + 4 * j;                // covers 0..287 over g,j
            float kv = __ldg(&k[r * 64 + co]);
            float e  = __expf(kv + 5.0f);
            sBrow[r] = __float2bfloat16(e - dw);
            pse += e; psk += kv;
        }
        float* red = reinterpret_cast<float*>(sm + OFF_R);
        red[g * 64 + co]       = pse;
        red[256 + g * 64 + co] = psk;
    }
    __syncthreads();

    // ---- C[co] (runs concurrent with MMA setup; read after post-MMA sync) ----
    float* sC = reinterpret_cast<float*>(sm + OFF_C);
    if (tid < 64) {
        const float* red = reinterpret_cast<const float*>(sm + OFF_R);
        float SE = red[tid] + red[64 + tid] + red[128 + tid] + red[192 + tid];
        float SK = red[256 + tid] + red[320 + tid] + red[384 + tid] + red[448 + tid];
        sC[tid] = SE - dxp[0] * SK + bias[tid];
    }

    // ---- 16 warps = 4(M) x 4(N); warp tile 16M x 16N; 2 K-chains ----
    const int wm = (wid & 3) * 16;
    const int wn = (wid >> 2) * 16;
    uint32_t aAddr = smb + OFF_A + (uint32_t)(wm + (lane & 15)) * STRB + (lane >> 4) * 16;
    uint32_t bAddr = smb + OFF_B + (uint32_t)(wn + (lane & 15)) * STRB + (lane >> 4) * 16;

    float acc0[8], acc1[8];
    #pragma unroll
    for (int i = 0; i < 8; i++) { acc0[i] = 0.f; acc1[i] = 0.f; }

    #pragma unroll
    for (int ks = 0; ks < 9; ks++) {
        uint32_t a0[4], b0[4], a1[4], b1[4];
        ldmx4(a0, aAddr + ks * 32);
        ldmx4(b0, bAddr + ks * 32);
        ldmx4(a1, aAddr + (ks + 9) * 32);
        ldmx4(b1, bAddr + (ks + 9) * 32);
        mma16816(acc0 + 0, a0, b0[0], b0[2]);
        mma16816(acc0 + 4, a0, b0[1], b0[3]);
        mma16816(acc1 + 0, a1, b1[0], b1[2]);
        mma16816(acc1 + 4, a1, b1[1], b1[3]);
    }
    #pragma unroll
    for (int i = 0; i < 8; i++) acc0[i] += acc1[i];

    // ---- epilogue: frags -> smem [co][j] (aliases A), coalesced STG ----
    __syncthreads();
    float* sD = reinterpret_cast<float*>(sm + OFF_A);   // stride 65
    {
        const int row  = lane >> 2;
        const int colp = (lane & 3) * 2;
        int j0 = wm + row, j1 = j0 + 8;
        #pragma unroll
        for (int jj = 0; jj < 2; jj++) {
            int co = wn + jj * 8 + colp;
            sD[(co    ) * 65 + j0] = acc0[jj * 4 + 0];
            sD[(co + 1) * 65 + j0] = acc0[jj * 4 + 1];
            sD[(co    ) * 65 + j1] = acc0[jj * 4 + 2];
            sD[(co + 1) * 65 + j1] = acc0[jj * 4 + 3];
        }
    }
    __syncthreads();
    {
        const int hw0 = ti * 56;             // = h0*28
        #pragma unroll
        for (int i = 0; i < 7; i++) {        // 64*56 = 3584 = 7*512
            int idx = i * CNT + tid;
            int co  = idx / 56;
            int j   = idx - co * 56;
            out[((size_t)(b * 64 + co)) * 784 + hw0 + j] = sD[co * 65 + j] + sC[co];
        }
    }
}

// ---------------- launch: ONE kernel ----------------
extern "C" void kernel_launch(void* const* d_in, const int* in_sizes, int n_in,
                              void* d_out, int out_size)
{
    (void)in_sizes; (void)n_in; (void)out_size;
    const float* x    = (const float*)d_in[0];
    const float* k    = (const float*)d_in[1];
    const float* bias = (const float*)d_in[2];
    const float* dx   = (const float*)d_in[3];
    const float* dw   = (const float*)d_in[4];
    float* out        = (float*)d_out;

    cudaFuncSetAttribute(fused_conv_kernel,
                         cudaFuncAttributeMaxDynamicSharedMemorySize, SMEMB);

    dim3 grid(14, 8);                        // 112 blocks, single wave
    fused_conv_kernel<<<grid, CNT, SMEMB>>>(x, k, bias, dx, dw, out);
}